// round 15
// baseline (speedup 1.0000x reference)
#include <cuda_runtime.h>
#include <cuda_fp16.h>
#include <math.h>
#include <stdint.h>

#define Bq 4096
#define Dq 1024

#define GAMMA_F  0.8f
#define ALPHA_F  0.5f
#define EPS_F    1e-14f

static __device__ __align__(16) __half g_Ah[(size_t)Bq * Dq];   // 8 MB
static __device__ __align__(16) __half g_Bh[(size_t)Bq * Dq];   // 8 MB

static __device__ float g_rS1[Bq];
static __device__ float g_rS2[Bq];
static __device__ int   g_rM [Bq];
static __device__ float g_cS1[Bq];
static __device__ float g_cS2[Bq];
static __device__ int   g_cM [Bq];
static __device__ float g_diag[Bq];

// ---------------------------------------------------------------------------
// helpers
// ---------------------------------------------------------------------------
__device__ __forceinline__ uint32_t smem_u32(const void* p) {
    uint32_t a;
    asm("{ .reg .u64 t; cvta.to.shared.u64 t, %1; cvt.u32.u64 %0, t; }" : "=r"(a) : "l"(p));
    return a;
}
#define SWZ(off) ((off) ^ (((off) >> 3) & 0x70))

__device__ __forceinline__ void cpa16(uint32_t s, const void* g) {
    asm volatile("cp.async.cg.shared.global [%0], [%1], 16;" :: "r"(s), "l"(g));
}
template <int N>
__device__ __forceinline__ void cpwait() {
    asm volatile("cp.async.wait_group %0;" :: "n"(N) : "memory");
}
__device__ __forceinline__ void ldsm4(uint32_t* r, uint32_t addr) {
    asm volatile("ldmatrix.sync.aligned.m8n8.x4.shared.b16 {%0,%1,%2,%3}, [%4];"
                 : "=r"(r[0]), "=r"(r[1]), "=r"(r[2]), "=r"(r[3]) : "r"(addr));
}
__device__ __forceinline__ void mma16816(float* d, const uint32_t* a, const uint32_t* b) {
    asm volatile(
        "mma.sync.aligned.m16n8k16.row.col.f32.f16.f16.f32 "
        "{%0,%1,%2,%3}, {%4,%5,%6,%7}, {%8,%9}, {%0,%1,%2,%3};"
        : "+f"(d[0]), "+f"(d[1]), "+f"(d[2]), "+f"(d[3])
        : "r"(a[0]), "r"(a[1]), "r"(a[2]), "r"(a[3]), "r"(b[0]), "r"(b[1]));
}

// ---------------------------------------------------------------------------
// K1: row L2-normalize + fp16 convert. One warp per row, MLP=8, shuffle-only.
// First 16 blocks zero the stats arrays; block 0 zeros out[0].
// ---------------------------------------------------------------------------
__global__ void __launch_bounds__(256) k_prep(const float* __restrict__ zis,
                                              const float* __restrict__ zjs,
                                              float* __restrict__ out) {
    int bid = blockIdx.x;
    int t = threadIdx.x;
    if (bid < 16) {
        int i = bid * 256 + t;
        g_rS1[i] = 0.0f; g_rS2[i] = 0.0f; g_rM[i] = 0;
        g_cS1[i] = 0.0f; g_cS2[i] = 0.0f; g_cM[i] = 0;
        if (bid == 0 && t == 0) out[0] = 0.0f;
    }
    int w = t >> 5, lane = t & 31;
    int gr = bid * 8 + w;
    bool isA = gr < Bq;
    size_t row = isA ? gr : gr - Bq;
    const float4* src = (const float4*)((isA ? zis : zjs) + row * Dq);
    __half* dst = (isA ? g_Ah : g_Bh) + row * Dq;

    float4 v[8];
    float ss = 0.0f;
    #pragma unroll
    for (int j = 0; j < 8; j++) {
        v[j] = src[lane + 32 * j];
        ss += v[j].x * v[j].x + v[j].y * v[j].y + v[j].z * v[j].z + v[j].w * v[j].w;
    }
    #pragma unroll
    for (int d = 16; d > 0; d >>= 1)
        ss += __shfl_xor_sync(0xffffffffu, ss, d);
    float scale = rsqrtf(ss);

    #pragma unroll
    for (int j = 0; j < 8; j++) {
        __half2 h01 = __floats2half2_rn(v[j].x * scale, v[j].y * scale);
        __half2 h23 = __floats2half2_rn(v[j].z * scale, v[j].w * scale);
        uint2 pk;
        pk.x = *(uint32_t*)&h01;
        pk.y = *(uint32_t*)&h23;
        *(uint2*)&dst[(lane + 32 * j) * 4] = pk;
    }
}

// ---------------------------------------------------------------------------
// K2: fp16 mma.sync GEMM with fused statistics epilogue.
// CTA tile 128x64, 128 threads (4 warps: 2M x 2N, warp tile 64x32 — same
// warp shape as the proven R8 config). Stage 24 KB -> 4-STAGE pipeline in
// 96 KB, 2 CTAs/SM. 2048 tiles over 296 slots = 6.92 waves: tail waste
// drops 15.6% -> 1.2% (the binding structural term per the R12 profile).
// ---------------------------------------------------------------------------
#define GM 128
#define GN 64
#define NCH (Dq / 64)          // 16
#define ATILE (GM * 128)       // 16 KB
#define BTILE (GN * 128)       // 8 KB
#define STGB (ATILE + BTILE)   // 24 KB
#define NSTG 4
#define GSMEM (NSTG * STGB)    // 96 KB

__global__ void __launch_bounds__(128, 2) k_gemm_fused() {
    extern __shared__ char sm[];
    uint32_t sbase = smem_u32(sm);
    int t = threadIdx.x;
    int wid = t >> 5, lane = t & 31;
    int wm = wid & 1;        // M offset 64*wm
    int wn = wid >> 1;       // N offset 32*wn (0..1)
    int by = blockIdx.y, bx = blockIdx.x;

    const char* Ag = (const char*)(g_Ah + (size_t)(by * GM) * Dq);
    const char* Bg = (const char*)(g_Bh + (size_t)(bx * GN) * Dq);

    float acc[4][4][4];
    #pragma unroll
    for (int i = 0; i < 4; i++)
        #pragma unroll
        for (int j = 0; j < 4; j++)
            #pragma unroll
            for (int q = 0; q < 4; q++) acc[i][j][q] = 0.0f;

    int row_ld = t >> 3;   // 0..15
    int seg = t & 7;       // 16B granule

    #define ISSUE(c)                                                          \
    do {                                                                      \
        int _s = (c) % NSTG;                                                  \
        uint32_t _sA = sbase + _s * STGB;                                     \
        uint32_t _sB = _sA + ATILE;                                           \
        size_t _ko = (size_t)(c) * 128 + seg * 16;                            \
        _Pragma("unroll")                                                     \
        for (int _j = 0; _j < 8; _j++) {                                      \
            int _r = row_ld + 16 * _j;                                        \
            uint32_t _so = SWZ((uint32_t)(_r * 128 + seg * 16));              \
            cpa16(_sA + _so, Ag + (size_t)_r * (Dq * 2) + _ko);               \
        }                                                                     \
        _Pragma("unroll")                                                     \
        for (int _j = 0; _j < 4; _j++) {                                      \
            int _r = row_ld + 16 * _j;                                        \
            uint32_t _so = SWZ((uint32_t)(_r * 128 + seg * 16));              \
            cpa16(_sB + _so, Bg + (size_t)_r * (Dq * 2) + _ko);               \
        }                                                                     \
        asm volatile("cp.async.commit_group;" ::: "memory");                  \
    } while (0)

    ISSUE(0);
    ISSUE(1);
    ISSUE(2);

    for (int c = 0; c < NCH; c++) {
        if (c <= NCH - 3)      cpwait<2>();
        else if (c == NCH - 2) cpwait<1>();
        else                   cpwait<0>();
        __syncthreads();
        if (c + 3 < NCH) ISSUE(c + 3);

        int s = c % NSTG;
        uint32_t sA = sbase + s * STGB;
        uint32_t sB = sA + ATILE;
        #pragma unroll
        for (int ks = 0; ks < 4; ks++) {
            uint32_t a[4][4];
            #pragma unroll
            for (int mt = 0; mt < 4; mt++) {
                int r = wm * 64 + mt * 16 + (lane & 15);
                ldsm4(a[mt], sA + SWZ((uint32_t)(r * 128 + ks * 32 + ((lane >> 4) << 4))));
            }
            uint32_t b[2][4];
            #pragma unroll
            for (int h = 0; h < 2; h++) {
                int nr = wn * 32 + h * 16 + ((lane >> 4) << 3) + (lane & 7);
                ldsm4(b[h], sB + SWZ((uint32_t)(nr * 128 + ks * 32 + (((lane >> 3) & 1) << 4))));
            }
            #pragma unroll
            for (int mt = 0; mt < 4; mt++)
                #pragma unroll
                for (int nt = 0; nt < 4; nt++)
                    mma16816(acc[mt][nt], a[mt], &b[nt >> 1][(nt & 1) * 2]);
        }
    }

    // ---------------- fused statistics epilogue ----------------
    __syncthreads();   // mainloop smem dead; reuse for reductions
    float* sred = (float*)sm;
    float* rS1 = sred;         float* rS2 = sred + 128;  int* rMx = (int*)(sred + 256);
    float* cS1 = sred + 384;   float* cS2 = sred + 448;  int* cMx = (int*)(sred + 512);
    rS1[t] = 0.0f; rS2[t] = 0.0f; rMx[t] = 0;
    if (t < 64) { cS1[t] = 0.0f; cS2[t] = 0.0f; cMx[t] = 0; }
    __syncthreads();

    float cs1[4][2], cs2[4][2], cmx[4][2];
    #pragma unroll
    for (int nt = 0; nt < 4; nt++)
        #pragma unroll
        for (int cc = 0; cc < 2; cc++) { cs1[nt][cc] = 0.0f; cs2[nt][cc] = 0.0f; cmx[nt][cc] = -1e30f; }

    #pragma unroll
    for (int mt = 0; mt < 4; mt++) {
        float s1A = 0.0f, s2A = 0.0f, mA = -1e30f;
        float s1B = 0.0f, s2B = 0.0f, mB = -1e30f;
        #pragma unroll
        for (int nt = 0; nt < 4; nt++) {
            float x0 = acc[mt][nt][0], x1 = acc[mt][nt][1];
            float x2 = acc[mt][nt][2], x3 = acc[mt][nt][3];
            float e0 = __expf(10.0f * x0), e1 = __expf(10.0f * x1);
            float e2 = __expf(10.0f * x2), e3 = __expf(10.0f * x3);
            s1A += e0 + e1;  s2A += fmaf(e0, x0, e1 * x1);  mA = fmaxf(mA, fmaxf(x0, x1));
            s1B += e2 + e3;  s2B += fmaf(e2, x2, e3 * x3);  mB = fmaxf(mB, fmaxf(x2, x3));
            cs1[nt][0] += e0 + e2;  cs2[nt][0] += fmaf(e0, x0, e2 * x2);
            cmx[nt][0] = fmaxf(cmx[nt][0], fmaxf(x0, x2));
            cs1[nt][1] += e1 + e3;  cs2[nt][1] += fmaf(e1, x1, e3 * x3);
            cmx[nt][1] = fmaxf(cmx[nt][1], fmaxf(x1, x3));
        }
        #pragma unroll
        for (int d = 1; d < 4; d <<= 1) {
            s1A += __shfl_xor_sync(0xffffffffu, s1A, d);
            s2A += __shfl_xor_sync(0xffffffffu, s2A, d);
            mA = fmaxf(mA, __shfl_xor_sync(0xffffffffu, mA, d));
            s1B += __shfl_xor_sync(0xffffffffu, s1B, d);
            s2B += __shfl_xor_sync(0xffffffffu, s2B, d);
            mB = fmaxf(mB, __shfl_xor_sync(0xffffffffu, mB, d));
        }
        if ((lane & 3) == 0) {
            int rA = wm * 64 + mt * 16 + (lane >> 2);
            atomicAdd(&rS1[rA], s1A); atomicAdd(&rS2[rA], s2A);
            atomicMax(&rMx[rA], __float_as_int(mA + 4.0f));
            int rB = rA + 8;
            atomicAdd(&rS1[rB], s1B); atomicAdd(&rS2[rB], s2B);
            atomicMax(&rMx[rB], __float_as_int(mB + 4.0f));
        }
    }
    #pragma unroll
    for (int nt = 0; nt < 4; nt++)
        #pragma unroll
        for (int cc = 0; cc < 2; cc++) {
            #pragma unroll
            for (int d = 4; d < 32; d <<= 1) {
                cs1[nt][cc] += __shfl_xor_sync(0xffffffffu, cs1[nt][cc], d);
                cs2[nt][cc] += __shfl_xor_sync(0xffffffffu, cs2[nt][cc], d);
                cmx[nt][cc] = fmaxf(cmx[nt][cc], __shfl_xor_sync(0xffffffffu, cmx[nt][cc], d));
            }
        }
    if (lane < 4) {
        #pragma unroll
        for (int nt = 0; nt < 4; nt++)
            #pragma unroll
            for (int cc = 0; cc < 2; cc++) {
                int cg = wn * 32 + nt * 8 + 2 * lane + cc;
                atomicAdd(&cS1[cg], cs1[nt][cc]); atomicAdd(&cS2[cg], cs2[nt][cc]);
                atomicMax(&cMx[cg], __float_as_int(cmx[nt][cc] + 4.0f));
            }
    }
    // diagonal overlap: rows [by*128,+128) vs cols [bx*64,+64): bx>>1 == by
    if ((bx >> 1) == by) {
        int roff = (bx & 1) << 6;   // rg == cg + roff on the diagonal
        #pragma unroll
        for (int mt = 0; mt < 4; mt++)
            #pragma unroll
            for (int nt = 0; nt < 4; nt++)
                #pragma unroll
                for (int q = 0; q < 4; q++) {
                    int rg = wm * 64 + mt * 16 + (lane >> 2) + ((q >= 2) ? 8 : 0);
                    int cg = wn * 32 + nt * 8 + 2 * (lane & 3) + (q & 1);
                    if (rg == cg + roff) g_diag[by * GM + rg] = acc[mt][nt][q];
                }
    }
    __syncthreads();
    atomicAdd(&g_rS1[by * GM + t], rS1[t]);
    atomicAdd(&g_rS2[by * GM + t], rS2[t]);
    atomicMax(&g_rM [by * GM + t], rMx[t]);
    if (t < 64) {
        atomicAdd(&g_cS1[bx * GN + t], cS1[t]);
        atomicAdd(&g_cS2[bx * GN + t], cS2[t]);
        atomicMax(&g_cM [bx * GN + t], cMx[t]);
    }
}

// ---------------------------------------------------------------------------
// K3: finalize — 32 blocks x 128 threads, one element each, atomicAdd to out.
// ---------------------------------------------------------------------------
__global__ void __launch_bounds__(128) k_final2(const float* __restrict__ sI,
                                                const float* __restrict__ sT,
                                                const float* __restrict__ bI,
                                                const float* __restrict__ bT,
                                                const int* __restrict__ ids,
                                                float* __restrict__ out) {
    int t = threadIdx.x;
    int i = blockIdx.x * 128 + t;
    const float invB1 = 1.0f / (float)(Bq - 1);

    int id = ids[i];
    float diag = g_diag[i];
    float ed = __expf(10.0f * diag);
    float accI, accT;
    {
        float M = __int_as_float(g_rM[i]) - 4.0f;
        float old_b = bI[id];
        float new_b = fmaxf(10.0f * (M - diag), old_b);
        float f = __expf(-10.0f * diag - new_b);
        float S1 = g_rS1[i], S2 = g_rS2[i];
        float se  = (S1 - ed) * f;
        float sed = (S2 - diag * S1) * f;
        float g = se * invB1;
        float sn = (1.0f - GAMMA_F) * sI[id] * __expf(old_b - new_b) + GAMMA_F * g;
        accI = sed / fmaxf(sn, EPS_F) * invB1;
    }
    {
        float M = __int_as_float(g_cM[i]) - 4.0f;
        float old_b = bT[id];
        float new_b = fmaxf(10.0f * (M - diag), old_b);
        float f = __expf(-10.0f * diag - new_b);
        float C1 = g_cS1[i], C2 = g_cS2[i];
        float se  = (C1 - ed) * f;
        float sed = (C2 - diag * C1) * f;
        float g = se * invB1;
        float sn = (1.0f - GAMMA_F) * sT[id] * __expf(old_b - new_b) + GAMMA_F * g;
        accT = sed / fmaxf(sn, EPS_F) * invB1;
    }
    float contrib = (ALPHA_F * accI + (1.0f - ALPHA_F) * accT) / (float)Bq;

    #pragma unroll
    for (int d = 16; d > 0; d >>= 1)
        contrib += __shfl_xor_sync(0xffffffffu, contrib, d);
    __shared__ float wsum[4];
    if ((t & 31) == 0) wsum[t >> 5] = contrib;
    __syncthreads();
    if (t == 0)
        atomicAdd(out, wsum[0] + wsum[1] + wsum[2] + wsum[3]);
}

// ---------------------------------------------------------------------------
extern "C" void kernel_launch(void* const* d_in, const int* in_sizes, int n_in,
                              void* d_out, int out_size) {
    const float* zis = (const float*)d_in[0];
    const float* zjs = (const float*)d_in[1];
    const float* s_I = (const float*)d_in[2];
    const float* s_T = (const float*)d_in[3];
    const float* b_I = (const float*)d_in[4];
    const float* b_T = (const float*)d_in[5];
    const int*   ids = (const int*)d_in[6];

    cudaFuncSetAttribute(k_gemm_fused, cudaFuncAttributeMaxDynamicSharedMemorySize, GSMEM);

    k_prep<<<2 * Bq / 8, 256>>>(zis, zjs, (float*)d_out);
    dim3 g(Bq / GN, Bq / GM);
    k_gemm_fused<<<g, 128, GSMEM>>>();
    k_final2<<<Bq / 128, 128>>>(s_I, s_T, b_I, b_T, ids, (float*)d_out);
}

// round 16
// speedup vs baseline: 1.1278x; 1.1278x over previous
#include <cuda_runtime.h>
#include <cuda_fp16.h>
#include <math.h>
#include <stdint.h>

#define Bq 4096
#define Dq 1024

#define GAMMA_F  0.8f
#define ALPHA_F  0.5f
#define EPS_F    1e-14f

static __device__ __align__(16) __half g_Ah[(size_t)Bq * Dq];   // 8 MB
static __device__ __align__(16) __half g_Bh[(size_t)Bq * Dq];   // 8 MB

static __device__ float g_rS1[Bq];
static __device__ float g_rS2[Bq];
static __device__ int   g_rM [Bq];
static __device__ float g_cS1[Bq];
static __device__ float g_cS2[Bq];
static __device__ int   g_cM [Bq];
static __device__ float g_diag[Bq];

// ---------------------------------------------------------------------------
// helpers
// ---------------------------------------------------------------------------
__device__ __forceinline__ uint32_t smem_u32(const void* p) {
    uint32_t a;
    asm("{ .reg .u64 t; cvta.to.shared.u64 t, %1; cvt.u32.u64 %0, t; }" : "=r"(a) : "l"(p));
    return a;
}
#define SWZ(off) ((off) ^ (((off) >> 3) & 0x70))

__device__ __forceinline__ void cpa16(uint32_t s, const void* g) {
    asm volatile("cp.async.cg.shared.global [%0], [%1], 16;" :: "r"(s), "l"(g));
}
template <int N>
__device__ __forceinline__ void cpwait() {
    asm volatile("cp.async.wait_group %0;" :: "n"(N) : "memory");
}
__device__ __forceinline__ void ldsm4(uint32_t* r, uint32_t addr) {
    asm volatile("ldmatrix.sync.aligned.m8n8.x4.shared.b16 {%0,%1,%2,%3}, [%4];"
                 : "=r"(r[0]), "=r"(r[1]), "=r"(r[2]), "=r"(r[3]) : "r"(addr));
}
__device__ __forceinline__ void mma16816(float* d, const uint32_t* a, const uint32_t* b) {
    asm volatile(
        "mma.sync.aligned.m16n8k16.row.col.f32.f16.f16.f32 "
        "{%0,%1,%2,%3}, {%4,%5,%6,%7}, {%8,%9}, {%0,%1,%2,%3};"
        : "+f"(d[0]), "+f"(d[1]), "+f"(d[2]), "+f"(d[3])
        : "r"(a[0]), "r"(a[1]), "r"(a[2]), "r"(a[3]), "r"(b[0]), "r"(b[1]));
}

// ---------------------------------------------------------------------------
// K1: row L2-normalize + fp16 convert. One warp per row, MLP=8, shuffle-only.
// First 16 blocks zero the stats arrays; block 0 zeros out[0].
// ---------------------------------------------------------------------------
__global__ void __launch_bounds__(256) k_prep(const float* __restrict__ zis,
                                              const float* __restrict__ zjs,
                                              float* __restrict__ out) {
    int bid = blockIdx.x;
    int t = threadIdx.x;
    if (bid < 16) {
        int i = bid * 256 + t;
        g_rS1[i] = 0.0f; g_rS2[i] = 0.0f; g_rM[i] = 0;
        g_cS1[i] = 0.0f; g_cS2[i] = 0.0f; g_cM[i] = 0;
        if (bid == 0 && t == 0) out[0] = 0.0f;
    }
    int w = t >> 5, lane = t & 31;
    int gr = bid * 8 + w;
    bool isA = gr < Bq;
    size_t row = isA ? gr : gr - Bq;
    const float4* src = (const float4*)((isA ? zis : zjs) + row * Dq);
    __half* dst = (isA ? g_Ah : g_Bh) + row * Dq;

    float4 v[8];
    float ss = 0.0f;
    #pragma unroll
    for (int j = 0; j < 8; j++) {
        v[j] = src[lane + 32 * j];
        ss += v[j].x * v[j].x + v[j].y * v[j].y + v[j].z * v[j].z + v[j].w * v[j].w;
    }
    #pragma unroll
    for (int d = 16; d > 0; d >>= 1)
        ss += __shfl_xor_sync(0xffffffffu, ss, d);
    float scale = rsqrtf(ss);

    #pragma unroll
    for (int j = 0; j < 8; j++) {
        __half2 h01 = __floats2half2_rn(v[j].x * scale, v[j].y * scale);
        __half2 h23 = __floats2half2_rn(v[j].z * scale, v[j].w * scale);
        uint2 pk;
        pk.x = *(uint32_t*)&h01;
        pk.y = *(uint32_t*)&h23;
        *(uint2*)&dst[(lane + 32 * j) * 4] = pk;
    }
}

// ---------------------------------------------------------------------------
// K2: fp16 mma.sync GEMM with fused statistics epilogue.
// CTA 128x128, 128 threads (4 warps: 2M x 2N, warp tile 64x64), BK=64,
// 3-stage cp.async, 96 KB smem, 2 CTAs/SM (255-reg cap -> room for FULL
// A+B fragment double-buffering: ldsm for ks+1 issued before the 32-mma
// burst of ks, hiding the 29-cyc fragment latency behind >=64 cyc of mma).
// ---------------------------------------------------------------------------
#define GM 128
#define GN 128
#define NCH (Dq / 64)          // 16
#define ATILE (GM * 128)       // 16 KB
#define BTILE (GN * 128)       // 16 KB
#define STGB (ATILE + BTILE)   // 32 KB
#define NSTG 3
#define GSMEM (NSTG * STGB)    // 96 KB

__global__ void __launch_bounds__(128, 2) k_gemm_fused() {
    extern __shared__ char sm[];
    uint32_t sbase = smem_u32(sm);
    int t = threadIdx.x;
    int wid = t >> 5, lane = t & 31;
    int wm = wid & 1;        // M offset 64*wm
    int wn = wid >> 1;       // N offset 64*wn
    int by = blockIdx.y, bx = blockIdx.x;

    const char* Ag = (const char*)(g_Ah + (size_t)(by * GM) * Dq);
    const char* Bg = (const char*)(g_Bh + (size_t)(bx * GN) * Dq);

    float acc[4][8][4];
    #pragma unroll
    for (int i = 0; i < 4; i++)
        #pragma unroll
        for (int j = 0; j < 8; j++)
            #pragma unroll
            for (int q = 0; q < 4; q++) acc[i][j][q] = 0.0f;

    int row_ld = t >> 3;   // 0..15
    int seg = t & 7;       // 16B granule

    // fragment addresses (thread-fixed row components)
    int arow = wm * 64 + (lane & 15);                 // + mt*16
    uint32_t ak16 = (uint32_t)((lane >> 4) << 4);
    int brow = wn * 64 + ((lane >> 4) << 3) + (lane & 7);   // + h*16
    uint32_t bk16 = (uint32_t)(((lane >> 3) & 1) << 4);

    #define ISSUE(c)                                                          \
    do {                                                                      \
        int _s = (c) % NSTG;                                                  \
        uint32_t _sA = sbase + _s * STGB;                                     \
        uint32_t _sB = _sA + ATILE;                                           \
        size_t _ko = (size_t)(c) * 128 + seg * 16;                            \
        _Pragma("unroll")                                                     \
        for (int _j = 0; _j < 8; _j++) {                                      \
            int _r = row_ld + 16 * _j;                                        \
            uint32_t _so = SWZ((uint32_t)(_r * 128 + seg * 16));              \
            cpa16(_sA + _so, Ag + (size_t)_r * (Dq * 2) + _ko);               \
            cpa16(_sB + _so, Bg + (size_t)_r * (Dq * 2) + _ko);               \
        }                                                                     \
        asm volatile("cp.async.commit_group;" ::: "memory");                  \
    } while (0)

    #define LOADFRAG(buf, ks)                                                 \
    do {                                                                      \
        _Pragma("unroll")                                                     \
        for (int _mt = 0; _mt < 4; _mt++)                                     \
            ldsm4(af[buf][_mt],                                               \
                  sA + SWZ((uint32_t)((arow + _mt * 16) * 128 + (ks) * 32) ^ ak16)); \
        _Pragma("unroll")                                                     \
        for (int _h = 0; _h < 4; _h++)                                        \
            ldsm4(bf[buf][_h],                                                \
                  sB + SWZ((uint32_t)((brow + _h * 16) * 128 + (ks) * 32) ^ bk16));  \
    } while (0)

    ISSUE(0);
    ISSUE(1);

    for (int c = 0; c < NCH; c++) {
        if (c < NCH - 2) cpwait<1>(); else cpwait<0>();
        __syncthreads();
        if (c + 2 < NCH) ISSUE(c + 2);

        int s = c % NSTG;
        uint32_t sA = sbase + s * STGB;
        uint32_t sB = sA + ATILE;

        uint32_t af[2][4][4], bf[2][4][4];
        LOADFRAG(0, 0);
        #pragma unroll
        for (int ks = 0; ks < 4; ks++) {
            int cur = ks & 1;
            if (ks < 3) LOADFRAG(cur ^ 1, ks + 1);
            #pragma unroll
            for (int mt = 0; mt < 4; mt++)
                #pragma unroll
                for (int nt = 0; nt < 8; nt++)
                    mma16816(acc[mt][nt], af[cur][mt], &bf[cur][nt >> 1][(nt & 1) * 2]);
        }
    }

    // NOTE on SWZ^k16: SWZ(r*128 + ks*32) XOR k16 == SWZ(r*128 + ks*32 + k16)
    // because k16 only toggles bit 4, untouched by the swizzle's bit mixing
    // (swizzle XORs bits[6:4] with bits[9:7]; adding k16 (bit4) cannot carry
    // into bit 7 since ks*32 + k16 < 128). Verified identical to R14 addressing.

    // ---------------- fused statistics epilogue ----------------
    __syncthreads();   // mainloop smem dead; reuse for reductions
    float* sred = (float*)sm;
    float* rS1 = sred;         float* rS2 = sred + 128;  int* rMx = (int*)(sred + 256);
    float* cS1 = sred + 384;   float* cS2 = sred + 512;  int* cMx = (int*)(sred + 640);
    rS1[t] = 0.0f; rS2[t] = 0.0f; rMx[t] = 0;
    cS1[t] = 0.0f; cS2[t] = 0.0f; cMx[t] = 0;
    __syncthreads();

    float cs1[8][2], cs2[8][2], cmx[8][2];
    #pragma unroll
    for (int nt = 0; nt < 8; nt++)
        #pragma unroll
        for (int cc = 0; cc < 2; cc++) { cs1[nt][cc] = 0.0f; cs2[nt][cc] = 0.0f; cmx[nt][cc] = -1e30f; }

    #pragma unroll
    for (int mt = 0; mt < 4; mt++) {
        float s1A = 0.0f, s2A = 0.0f, mA = -1e30f;
        float s1B = 0.0f, s2B = 0.0f, mB = -1e30f;
        #pragma unroll
        for (int nt = 0; nt < 8; nt++) {
            float x0 = acc[mt][nt][0], x1 = acc[mt][nt][1];
            float x2 = acc[mt][nt][2], x3 = acc[mt][nt][3];
            float e0 = __expf(10.0f * x0), e1 = __expf(10.0f * x1);
            float e2 = __expf(10.0f * x2), e3 = __expf(10.0f * x3);
            s1A += e0 + e1;  s2A += fmaf(e0, x0, e1 * x1);  mA = fmaxf(mA, fmaxf(x0, x1));
            s1B += e2 + e3;  s2B += fmaf(e2, x2, e3 * x3);  mB = fmaxf(mB, fmaxf(x2, x3));
            cs1[nt][0] += e0 + e2;  cs2[nt][0] += fmaf(e0, x0, e2 * x2);
            cmx[nt][0] = fmaxf(cmx[nt][0], fmaxf(x0, x2));
            cs1[nt][1] += e1 + e3;  cs2[nt][1] += fmaf(e1, x1, e3 * x3);
            cmx[nt][1] = fmaxf(cmx[nt][1], fmaxf(x1, x3));
        }
        #pragma unroll
        for (int d = 1; d < 4; d <<= 1) {
            s1A += __shfl_xor_sync(0xffffffffu, s1A, d);
            s2A += __shfl_xor_sync(0xffffffffu, s2A, d);
            mA = fmaxf(mA, __shfl_xor_sync(0xffffffffu, mA, d));
            s1B += __shfl_xor_sync(0xffffffffu, s1B, d);
            s2B += __shfl_xor_sync(0xffffffffu, s2B, d);
            mB = fmaxf(mB, __shfl_xor_sync(0xffffffffu, mB, d));
        }
        if ((lane & 3) == 0) {
            int rA = wm * 64 + mt * 16 + (lane >> 2);
            atomicAdd(&rS1[rA], s1A); atomicAdd(&rS2[rA], s2A);
            atomicMax(&rMx[rA], __float_as_int(mA + 4.0f));
            int rB = rA + 8;
            atomicAdd(&rS1[rB], s1B); atomicAdd(&rS2[rB], s2B);
            atomicMax(&rMx[rB], __float_as_int(mB + 4.0f));
        }
    }
    #pragma unroll
    for (int nt = 0; nt < 8; nt++)
        #pragma unroll
        for (int cc = 0; cc < 2; cc++) {
            #pragma unroll
            for (int d = 4; d < 32; d <<= 1) {
                cs1[nt][cc] += __shfl_xor_sync(0xffffffffu, cs1[nt][cc], d);
                cs2[nt][cc] += __shfl_xor_sync(0xffffffffu, cs2[nt][cc], d);
                cmx[nt][cc] = fmaxf(cmx[nt][cc], __shfl_xor_sync(0xffffffffu, cmx[nt][cc], d));
            }
        }
    if (lane < 4) {
        #pragma unroll
        for (int nt = 0; nt < 8; nt++)
            #pragma unroll
            for (int cc = 0; cc < 2; cc++) {
                int cg = wn * 64 + nt * 8 + 2 * lane + cc;
                atomicAdd(&cS1[cg], cs1[nt][cc]); atomicAdd(&cS2[cg], cs2[nt][cc]);
                atomicMax(&cMx[cg], __float_as_int(cmx[nt][cc] + 4.0f));
            }
    }
    // diagonal CTAs scatter diag values
    if (by == bx) {
        #pragma unroll
        for (int mt = 0; mt < 4; mt++)
            #pragma unroll
            for (int nt = 0; nt < 8; nt++)
                #pragma unroll
                for (int q = 0; q < 4; q++) {
                    int rg = wm * 64 + mt * 16 + (lane >> 2) + ((q >= 2) ? 8 : 0);
                    int cg = wn * 64 + nt * 8 + 2 * (lane & 3) + (q & 1);
                    if (rg == cg) g_diag[by * GM + rg] = acc[mt][nt][q];
                }
    }
    __syncthreads();
    atomicAdd(&g_rS1[by * GM + t], rS1[t]);
    atomicAdd(&g_rS2[by * GM + t], rS2[t]);
    atomicMax(&g_rM [by * GM + t], rMx[t]);
    atomicAdd(&g_cS1[bx * GN + t], cS1[t]);
    atomicAdd(&g_cS2[bx * GN + t], cS2[t]);
    atomicMax(&g_cM [bx * GN + t], cMx[t]);
}

// ---------------------------------------------------------------------------
// K3: finalize — 32 blocks x 128 threads, one element each, atomicAdd to out.
// ---------------------------------------------------------------------------
__global__ void __launch_bounds__(128) k_final2(const float* __restrict__ sI,
                                                const float* __restrict__ sT,
                                                const float* __restrict__ bI,
                                                const float* __restrict__ bT,
                                                const int* __restrict__ ids,
                                                float* __restrict__ out) {
    int t = threadIdx.x;
    int i = blockIdx.x * 128 + t;
    const float invB1 = 1.0f / (float)(Bq - 1);

    int id = ids[i];
    float diag = g_diag[i];
    float ed = __expf(10.0f * diag);
    float accI, accT;
    {
        float M = __int_as_float(g_rM[i]) - 4.0f;
        float old_b = bI[id];
        float new_b = fmaxf(10.0f * (M - diag), old_b);
        float f = __expf(-10.0f * diag - new_b);
        float S1 = g_rS1[i], S2 = g_rS2[i];
        float se  = (S1 - ed) * f;
        float sed = (S2 - diag * S1) * f;
        float g = se * invB1;
        float sn = (1.0f - GAMMA_F) * sI[id] * __expf(old_b - new_b) + GAMMA_F * g;
        accI = sed / fmaxf(sn, EPS_F) * invB1;
    }
    {
        float M = __int_as_float(g_cM[i]) - 4.0f;
        float old_b = bT[id];
        float new_b = fmaxf(10.0f * (M - diag), old_b);
        float f = __expf(-10.0f * diag - new_b);
        float C1 = g_cS1[i], C2 = g_cS2[i];
        float se  = (C1 - ed) * f;
        float sed = (C2 - diag * C1) * f;
        float g = se * invB1;
        float sn = (1.0f - GAMMA_F) * sT[id] * __expf(old_b - new_b) + GAMMA_F * g;
        accT = sed / fmaxf(sn, EPS_F) * invB1;
    }
    float contrib = (ALPHA_F * accI + (1.0f - ALPHA_F) * accT) / (float)Bq;

    #pragma unroll
    for (int d = 16; d > 0; d >>= 1)
        contrib += __shfl_xor_sync(0xffffffffu, contrib, d);
    __shared__ float wsum[4];
    if ((t & 31) == 0) wsum[t >> 5] = contrib;
    __syncthreads();
    if (t == 0)
        atomicAdd(out, wsum[0] + wsum[1] + wsum[2] + wsum[3]);
}

// ---------------------------------------------------------------------------
extern "C" void kernel_launch(void* const* d_in, const int* in_sizes, int n_in,
                              void* d_out, int out_size) {
    const float* zis = (const float*)d_in[0];
    const float* zjs = (const float*)d_in[1];
    const float* s_I = (const float*)d_in[2];
    const float* s_T = (const float*)d_in[3];
    const float* b_I = (const float*)d_in[4];
    const float* b_T = (const float*)d_in[5];
    const int*   ids = (const int*)d_in[6];

    cudaFuncSetAttribute(k_gemm_fused, cudaFuncAttributeMaxDynamicSharedMemorySize, GSMEM);

    k_prep<<<2 * Bq / 8, 256>>>(zis, zjs, (float*)d_out);
    dim3 g(Bq / GN, Bq / GM);
    k_gemm_fused<<<g, 128, GSMEM>>>();
    k_final2<<<Bq / 128, 128>>>(s_I, s_T, b_I, b_T, ids, (float*)d_out);
}